// round 16
// baseline (speedup 1.0000x reference)
#include <cuda_runtime.h>

#define TT   2048
#define DD   64
#define HH   64
#define NG   256
#define WIN  8                 // steps per window
#define NWINS (TT / WIN)       // 256
#define RING 32                // xg ring slots (4 windows)

// Dynamic SMEM layout (floats):
//  XGR: [2][RING][NG]      xg ring per batch (float2-packed gate pairs)
//  XST: [4][2][WIN][DD]    x stage ring (4 windows)
//  HS : [2][2][HH]         h double buffer
#define XGR_OFF 0
#define XST_OFF 16384
#define HS_OFF  (16384 + 4096)
#define SMEM_FLOATS (HS_OFF + 256)
#define SMEM_BYTES  (SMEM_FLOATS * 4)   // 82,944 B

__device__ __forceinline__ unsigned long long ffma2(unsigned long long a,
                                                    unsigned long long b,
                                                    unsigned long long c) {
    unsigned long long d;
    asm("fma.rn.f32x2 %0, %1, %2, %3;" : "=l"(d) : "l"(a), "l"(b), "l"(c));
    return d;
}
__device__ __forceinline__ unsigned long long add2(unsigned long long a,
                                                   unsigned long long b) {
    unsigned long long d;
    asm("add.rn.f32x2 %0, %1, %2;" : "=l"(d) : "l"(a), "l"(b));
    return d;
}
__device__ __forceinline__ float red2(unsigned long long v) {
    float lo, hi;
    asm("mov.b64 {%0, %1}, %2;" : "=f"(lo), "=f"(hi) : "l"(v));
    return lo + hi;
}
__device__ __forceinline__ float tanh_ap(float x) {
    float y;
    asm("tanh.approx.f32 %0, %1;" : "=f"(y) : "f"(x));
    return y;
}

// ---------------------------------------------------------------------------
// R12 skeleton. grid=128, block=256.
//   warps 0-3  (tid 0..127): recurrence for 2 batches, xg from SMEM ring
//                            (float2 gate pairs read at step top),
//                            bar.sync 1,128 per step.
//   warps 4-7  (tid 128..255): producer — xg = bias + W_ih . x for the same
//                            2 batches, 3 windows ahead into the ring;
//                            x staged GMEM->SMEM 4 windows ahead.
//   __syncthreads() once per 8-step window joins the two sides.
// ---------------------------------------------------------------------------
__global__ void __launch_bounds__(256, 1)
lstm_ws(const float* __restrict__ x, const float* __restrict__ w_ih,
        const float* __restrict__ w_hh, const float* __restrict__ b_ih,
        const float* __restrict__ b_hh, const float* __restrict__ fc_w,
        const float* __restrict__ fc_b, float* __restrict__ out)
{
    extern __shared__ __align__(16) float sm[];
    float* XGR = sm + XGR_OFF;   // [bb][slot][float2 gate-pair]
    float* XST = sm + XST_OFF;   // [sslot][bb][t'][k]
    float* HS  = sm + HS_OFF;    // [buf][bb][u]

    const int tid = threadIdx.x;
    const int b0  = blockIdx.x * 2;
    const bool is_rec = (tid < 128);

    // ---------- prologue: cooperatively stage x windows 0..3 ----------
    {
#pragma unroll
        for (int r = 0; r < 4; ++r) {
            int idx = tid + r * 256;            // 0..1023 float4s
            int win = idx >> 8;
            int wi  = idx & 255;
            int bb  = wi >> 7;
            int rem = wi & 127;
            int tq  = rem >> 4;
            int q   = rem & 15;
            float4 v = ((const float4*)(x +
                        ((size_t)(b0 + bb) * TT + win * WIN + tq) * DD))[q];
            ((float4*)(XST + win * (2 * WIN * DD)))[wi] = v;
        }
    }
    __syncthreads();

    // =====================  REC side state  =====================
    int u = 0, role = 0, ga = 0, gb = 0;
    ulonglong2 wa[16], wb[16];
    float kb = 0.f, sc = 0.f, off = 0.f;
    // =====================  PROD side state =====================
    int pt = tid - 128;
    int pga = pt, pgb = pt + 128;
    ulonglong2 wpa[16], wpb[16];
    float bpa = 0.f, bpb = 0.f;

    if (is_rec) {
        u = tid >> 1; role = tid & 1;
        ga = u + 64 * role; gb = ga + 128;
        const ulonglong2* pwa = (const ulonglong2*)(w_hh + ga * HH);
        const ulonglong2* pwb = (const ulonglong2*)(w_hh + gb * HH);
#pragma unroll
        for (int j = 0; j < 16; ++j) { wa[j] = pwa[j]; wb[j] = pwb[j]; }
        kb  = role ? 0.5f : 1.f;
        sc  = role ? 0.5f : 1.f;
        off = role ? 0.5f : 0.f;
        if (tid < 64) {
            HS[tid] = 0.f; HS[64 + tid] = 0.f;
            HS[128 + tid] = 0.f; HS[192 + tid] = 0.f;
        }
    } else {
        const ulonglong2* pa = (const ulonglong2*)(w_ih + (size_t)pga * DD);
        const ulonglong2* pb = (const ulonglong2*)(w_ih + (size_t)pgb * DD);
#pragma unroll
        for (int j = 0; j < 16; ++j) { wpa[j] = pa[j]; wpb[j] = pb[j]; }
        bpa = b_ih[pga] + b_hh[pga];
        bpb = b_ih[pgb] + b_hh[pgb];

        // prologue: compute windows 0,1,2 into the xg ring (float2-packed)
        for (int wc = 0; wc < 3; ++wc) {
            const float* xw = XST + (wc & 3) * (2 * WIN * DD);
#pragma unroll
            for (int bb = 0; bb < 2; ++bb) {
                unsigned long long aa[8], ab[8];
#pragma unroll
                for (int i = 0; i < 8; ++i) { aa[i] = 0ull; ab[i] = 0ull; }
#pragma unroll
                for (int j = 0; j < 16; ++j) {
                    ulonglong2 wja = wpa[j], wjb = wpb[j];
#pragma unroll
                    for (int i = 0; i < 8; ++i) {
                        ulonglong2 xv = *(const ulonglong2*)(xw + bb * WIN * DD
                                                             + i * DD + j * 4);
                        aa[i] = ffma2(wja.x, xv.x, aa[i]);
                        aa[i] = ffma2(wja.y, xv.y, aa[i]);
                        ab[i] = ffma2(wjb.x, xv.x, ab[i]);
                        ab[i] = ffma2(wjb.y, xv.y, ab[i]);
                    }
                }
#pragma unroll
                for (int i = 0; i < 8; ++i) {
                    int slot = (wc * WIN + i) & (RING - 1);
                    ((float2*)(XGR + bb * (RING * NG) + slot * NG))[pga] =
                        make_float2(bpa + red2(aa[i]), bpb + red2(ab[i]));
                }
            }
        }
    }
    __syncthreads();

    float c0s = 0.f, c1s = 0.f;   // rec cell states

    for (int w = 0; w < NWINS; ++w) {
        if (is_rec) {
            // ---------------- 8 recurrence steps ----------------
#pragma unroll
            for (int i = 0; i < 8; ++i) {
                const int t = w * WIN + i;
                const int slot = t & (RING - 1);

                // xg for this step: one LDS.64 per batch (float2 gate pair)
                float2 cur0 = ((const float2*)(XGR + slot * NG))[ga];
                float2 cur1 = ((const float2*)(XGR + RING * NG + slot * NG))[ga];

                const ulonglong2* hv0 = (const ulonglong2*)(HS + (t & 1) * 128);
                const ulonglong2* hv1 = hv0 + 16;   // batch 1 (+64 floats)
                unsigned long long A0 = 0ull, A1 = 0ull, C0 = 0ull, C1 = 0ull;
                unsigned long long D0 = 0ull, D1 = 0ull, E0 = 0ull, E1 = 0ull;
#pragma unroll
                for (int j = 0; j < 16; ++j) {
                    ulonglong2 h20 = hv0[j];
                    ulonglong2 h21 = hv1[j];
                    A0 = ffma2(wa[j].x, h20.x, A0);
                    A1 = ffma2(wa[j].y, h20.y, A1);
                    C0 = ffma2(wb[j].x, h20.x, C0);
                    C1 = ffma2(wb[j].y, h20.y, C1);
                    D0 = ffma2(wa[j].x, h21.x, D0);
                    D1 = ffma2(wa[j].y, h21.y, D1);
                    E0 = ffma2(wb[j].x, h21.x, E0);
                    E1 = ffma2(wb[j].y, h21.y, E1);
                }
                float sa0 = cur0.x + red2(add2(A0, A1));
                float sb0 = cur0.y + red2(add2(C0, C1));
                float sa1 = cur1.x + red2(add2(D0, D1));
                float sb1 = cur1.y + red2(add2(E0, E1));

                float Aq0 = fmaf(0.5f, tanh_ap(0.5f * sa0), 0.5f);
                float Bv0 = fmaf(sc, tanh_ap(kb * sb0), off);
                float pr0 = Aq0 * Bv0;
                float sd0 = role ? Aq0 : pr0;
                float Aq1 = fmaf(0.5f, tanh_ap(0.5f * sa1), 0.5f);
                float Bv1 = fmaf(sc, tanh_ap(kb * sb1), off);
                float pr1 = Aq1 * Bv1;
                float sd1 = role ? Aq1 : pr1;

                float rv0 = __shfl_xor_sync(0xFFFFFFFFu, sd0, 1);
                float rv1 = __shfl_xor_sync(0xFFFFFFFFu, sd1, 1);

                float cm0 = role ? Aq0 : rv0, cd0 = role ? rv0 : pr0;
                float cm1 = role ? Aq1 : rv1, cd1 = role ? rv1 : pr1;
                c0s = fmaf(cm0, c0s, cd0);
                c1s = fmaf(cm1, c1s, cd1);
                float th0 = tanh_ap(c0s);
                float th1 = tanh_ap(c1s);
                if (role) {
                    HS[((t + 1) & 1) * 128 + u]      = Bv0 * th0;
                    HS[((t + 1) & 1) * 128 + 64 + u] = Bv1 * th1;
                }
                asm volatile("bar.sync 1, 128;");
            }
        } else {
            // ---------------- producer ----------------
            const int wl = w + 4;          // window to stage
            const int wc = w + 3;          // window to compute
            float4 r0, r1;
            if (wl < NWINS) {
                int idx0 = pt, idx1 = pt + 128;
                int bb0 = idx0 >> 7, tq0 = (idx0 & 127) >> 4, q0 = idx0 & 15;
                int bb1 = idx1 >> 7, tq1 = (idx1 & 127) >> 4, q1 = idx1 & 15;
                r0 = ((const float4*)(x + ((size_t)(b0 + bb0) * TT
                                           + wl * WIN + tq0) * DD))[q0];
                r1 = ((const float4*)(x + ((size_t)(b0 + bb1) * TT
                                           + wl * WIN + tq1) * DD))[q1];
            }
            if (wc < NWINS) {
                const float* xw = XST + (wc & 3) * (2 * WIN * DD);
#pragma unroll
                for (int bb = 0; bb < 2; ++bb) {
                    unsigned long long aa[8], ab[8];
#pragma unroll
                    for (int i = 0; i < 8; ++i) { aa[i] = 0ull; ab[i] = 0ull; }
#pragma unroll
                    for (int j = 0; j < 16; ++j) {
                        ulonglong2 wja = wpa[j], wjb = wpb[j];
#pragma unroll
                        for (int i = 0; i < 8; ++i) {
                            ulonglong2 xv = *(const ulonglong2*)(xw
                                            + bb * WIN * DD + i * DD + j * 4);
                            aa[i] = ffma2(wja.x, xv.x, aa[i]);
                            aa[i] = ffma2(wja.y, xv.y, aa[i]);
                            ab[i] = ffma2(wjb.x, xv.x, ab[i]);
                            ab[i] = ffma2(wjb.y, xv.y, ab[i]);
                        }
                    }
#pragma unroll
                    for (int i = 0; i < 8; ++i) {
                        int slot = (wc * WIN + i) & (RING - 1);
                        ((float2*)(XGR + bb * (RING * NG) + slot * NG))[pga] =
                            make_float2(bpa + red2(aa[i]), bpb + red2(ab[i]));
                    }
                }
            }
            if (wl < NWINS) {   // stage into slot wl&3 == w&3 (window w's x is dead)
                float4* dst = (float4*)(XST + (wl & 3) * (2 * WIN * DD));
                dst[pt]       = r0;
                dst[pt + 128] = r1;
            }
        }
        __syncthreads();
    }

    // ---- final FC: out[b, o] = h_last . fc_w[o] + fc_b[o] ----
    if (tid < 16) {
        int bb = tid >> 3, o = tid & 7;
        const float* hfin = HS + (TT & 1) * 128 + bb * 64;
        float s = fc_b[o];
#pragma unroll
        for (int k = 0; k < HH; ++k) s += hfin[k] * fc_w[o * HH + k];
        out[(b0 + bb) * 8 + o] = s;
    }
}

extern "C" void kernel_launch(void* const* d_in, const int* in_sizes, int n_in,
                              void* d_out, int out_size) {
    const float* x    = (const float*)d_in[0];
    const float* w_ih = (const float*)d_in[1];
    const float* w_hh = (const float*)d_in[2];
    const float* b_ih = (const float*)d_in[3];
    const float* b_hh = (const float*)d_in[4];
    const float* fc_w = (const float*)d_in[5];
    const float* fc_b = (const float*)d_in[6];
    float* out = (float*)d_out;

    const int B = in_sizes[0] / (TT * DD);   // 256

    static int attr_done = 0;
    if (!attr_done) {
        cudaFuncSetAttribute(lstm_ws,
                             cudaFuncAttributeMaxDynamicSharedMemorySize,
                             SMEM_BYTES);
        attr_done = 1;
    }
    lstm_ws<<<B / 2, 256, SMEM_BYTES>>>(x, w_ih, w_hh, b_ih, b_hh,
                                        fc_w, fc_b, out);
}